// round 1
// baseline (speedup 1.0000x reference)
#include <cuda_runtime.h>
#include <cstdint>

#define N_NODES 50000
#define N_EDGES 1600000
#define D 128

// Scratch (allocation-free rule: __device__ globals)
__device__ float g_y[(size_t)N_NODES * D];   // y = x @ W  (25.6 MB)
__device__ float g_deg[N_NODES];
__device__ float g_dis[N_NODES];

// ---------------------------------------------------------------------------
__global__ void zero_deg_kernel() {
    int i = blockIdx.x * blockDim.x + threadIdx.x;
    if (i < N_NODES) g_deg[i] = 0.0f;
}

__global__ void count_deg_kernel(const int* __restrict__ row) {
    int i = blockIdx.x * blockDim.x + threadIdx.x;
    if (i < N_EDGES) atomicAdd(&g_deg[row[i]], 1.0f);
}

__global__ void rsqrt_kernel() {
    int i = blockIdx.x * blockDim.x + threadIdx.x;
    if (i < N_NODES) g_dis[i] = rsqrtf(g_deg[i]);   // deg=0 -> inf, matches ref
}

// ---------------------------------------------------------------------------
// y = x @ W   (50000x128 @ 128x128, fp32).  BM=128 rows per block, full N=128.
// 256 threads, each computes an 8x8 micro-tile. K chunked by 32 (32 KB smem).
__global__ __launch_bounds__(256) void gemm_kernel(const float* __restrict__ x,
                                                   const float* __restrict__ W) {
    __shared__ float xs[128][33];   // padded: a-reads conflict-free
    __shared__ float ws[32][128];

    const int tid  = threadIdx.x;
    const int tr   = (tid >> 4) << 3;   // 0..120, row offset of micro-tile
    const int tc   = (tid & 15) << 3;   // 0..120, col offset
    const int row0 = blockIdx.x * 128;

    float acc[8][8];
#pragma unroll
    for (int i = 0; i < 8; i++)
#pragma unroll
        for (int j = 0; j < 8; j++) acc[i][j] = 0.0f;

    for (int kk = 0; kk < 128; kk += 32) {
        // load x tile: 128 rows x 32 cols (1024 float4, 4 per thread)
#pragma unroll
        for (int i = 0; i < 4; i++) {
            int f4 = tid + i * 256;
            int r  = f4 >> 3;
            int kc = (f4 & 7) << 2;
            int gr = row0 + r;
            float4 v = make_float4(0.f, 0.f, 0.f, 0.f);
            if (gr < N_NODES)
                v = *(const float4*)&x[(size_t)gr * D + kk + kc];
            xs[r][kc + 0] = v.x; xs[r][kc + 1] = v.y;
            xs[r][kc + 2] = v.z; xs[r][kc + 3] = v.w;
        }
        // load W tile: 32 rows x 128 cols
#pragma unroll
        for (int i = 0; i < 4; i++) {
            int f4 = tid + i * 256;
            int r  = f4 >> 5;
            int cc = (f4 & 31) << 2;
            *(float4*)&ws[r][cc] = *(const float4*)&W[(size_t)(kk + r) * D + cc];
        }
        __syncthreads();

#pragma unroll
        for (int k = 0; k < 32; k++) {
            float a[8], b[8];
#pragma unroll
            for (int i = 0; i < 8; i++) a[i] = xs[tr + i][k];
#pragma unroll
            for (int j = 0; j < 8; j++) b[j] = ws[k][tc + j];
#pragma unroll
            for (int i = 0; i < 8; i++)
#pragma unroll
                for (int j = 0; j < 8; j++) acc[i][j] = fmaf(a[i], b[j], acc[i][j]);
        }
        __syncthreads();
    }

#pragma unroll
    for (int i = 0; i < 8; i++) {
        int gr = row0 + tr + i;
        if (gr < N_NODES) {
            float* dst = &g_y[(size_t)gr * D + tc];
            *(float4*)&dst[0] = make_float4(acc[i][0], acc[i][1], acc[i][2], acc[i][3]);
            *(float4*)&dst[4] = make_float4(acc[i][4], acc[i][5], acc[i][6], acc[i][7]);
        }
    }
}

// ---------------------------------------------------------------------------
// out[n][:] = bias[:]   (scatter then accumulates directly into out)
__global__ void init_out_kernel(const float* __restrict__ bias, float4* __restrict__ out4) {
    int i = blockIdx.x * blockDim.x + threadIdx.x;   // N_NODES*32 float4's
    if (i < N_NODES * (D / 4)) {
        const float4* b4 = (const float4*)bias;
        out4[i] = b4[i & 31];
    }
}

// ---------------------------------------------------------------------------
// One warp per edge: out[row] += dis[row]*dis[col] * y[col]
// Lane l handles floats [4l..4l+3] via red.global.add.v4.f32 (no return value).
__global__ __launch_bounds__(256) void scatter_kernel(const int* __restrict__ row,
                                                      const int* __restrict__ col,
                                                      float* __restrict__ out) {
    int gw   = (blockIdx.x * blockDim.x + threadIdx.x) >> 5;
    int lane = threadIdx.x & 31;
    if (gw >= N_EDGES) return;

    int r = row[gw];
    int c = col[gw];
    float w = g_dis[r] * g_dis[c];

    const float4 v = *(const float4*)&g_y[(size_t)c * D + lane * 4];
    float* dst = out + (size_t)r * D + lane * 4;

    asm volatile("red.global.add.v4.f32 [%0], {%1, %2, %3, %4};"
                 :: "l"(dst), "f"(v.x * w), "f"(v.y * w), "f"(v.z * w), "f"(v.w * w)
                 : "memory");
}

// ---------------------------------------------------------------------------
extern "C" void kernel_launch(void* const* d_in, const int* in_sizes, int n_in,
                              void* d_out, int out_size) {
    const float* x       = (const float*)d_in[0];
    const float* weight  = (const float*)d_in[1];
    const float* bias    = (const float*)d_in[2];
    const int*   edgerow = (const int*)d_in[3];
    const int*   edgecol = (const int*)d_in[4];
    float*       out     = (float*)d_out;

    zero_deg_kernel<<<(N_NODES + 255) / 256, 256>>>();
    count_deg_kernel<<<(N_EDGES + 255) / 256, 256>>>(edgerow);
    rsqrt_kernel<<<(N_NODES + 255) / 256, 256>>>();

    gemm_kernel<<<(N_NODES + 127) / 128, 256>>>(x, weight);

    init_out_kernel<<<(N_NODES * (D / 4) + 255) / 256, 256>>>(bias, (float4*)out);

    // one warp per edge -> 8 edges per 256-thread block
    scatter_kernel<<<(N_EDGES + 7) / 8, 256>>>(edgerow, edgecol, out);
}

// round 2
// speedup vs baseline: 1.0571x; 1.0571x over previous
#include <cuda_runtime.h>
#include <cstdint>

#define N_NODES 50000
#define N_EDGES 1600000
#define D 128

// Scratch (__device__ globals per allocation rules)
__device__ float g_y[(size_t)N_NODES * D];    // y = x @ W  (25.6 MB)
__device__ int   g_cnt[N_NODES];
__device__ float g_dis[N_NODES];
__device__ int   g_ptr[N_NODES + 1];
__device__ int   g_cur[N_NODES];
__device__ int   g_ecol[N_EDGES];

// ---------------------------------------------------------------------------
__global__ void zero_cnt_kernel() {
    int i = blockIdx.x * blockDim.x + threadIdx.x;
    if (i < N_NODES) g_cnt[i] = 0;
}

__global__ void count_kernel(const int* __restrict__ row) {
    int i = blockIdx.x * blockDim.x + threadIdx.x;
    if (i < N_EDGES) atomicAdd(&g_cnt[row[i]], 1);
}

__global__ void rsqrt_kernel() {
    int i = blockIdx.x * blockDim.x + threadIdx.x;
    if (i < N_NODES) g_dis[i] = rsqrtf((float)g_cnt[i]);   // deg=0 -> inf (matches ref)
}

// Single-block exclusive scan over g_cnt -> g_ptr / g_cur (1024 thr, chunked)
__global__ __launch_bounds__(1024) void scan_kernel() {
    __shared__ int s[1024];
    __shared__ int carry;
    int tid = threadIdx.x;
    if (tid == 0) carry = 0;
    __syncthreads();

    for (int base = 0; base < N_NODES; base += 1024) {
        int v = (base + tid < N_NODES) ? g_cnt[base + tid] : 0;
        s[tid] = v;
        __syncthreads();
#pragma unroll
        for (int off = 1; off < 1024; off <<= 1) {
            int t = (tid >= off) ? s[tid - off] : 0;
            __syncthreads();
            s[tid] += t;
            __syncthreads();
        }
        int excl = s[tid] - v;
        int c = carry;
        if (base + tid < N_NODES) {
            g_ptr[base + tid] = c + excl;
            g_cur[base + tid] = c + excl;
        }
        __syncthreads();
        if (tid == 0) carry = c + s[1023];
        __syncthreads();
    }
    if (tid == 0) g_ptr[N_NODES] = N_EDGES;
}

__global__ void fill_kernel(const int* __restrict__ row, const int* __restrict__ col) {
    int i = blockIdx.x * blockDim.x + threadIdx.x;
    if (i < N_EDGES) {
        int r = row[i];
        int p = atomicAdd(&g_cur[r], 1);
        g_ecol[p] = col[i];
    }
}

// ---------------------------------------------------------------------------
// y = x @ W  (50000x128 @ 128x128 fp32).  BM=128, 512 threads, 4x8 micro-tile.
__global__ __launch_bounds__(512) void gemm_kernel(const float* __restrict__ x,
                                                   const float* __restrict__ W) {
    __shared__ float xs[128][33];
    __shared__ float ws[32][128];

    const int tid  = threadIdx.x;
    const int tr   = (tid >> 4) << 2;   // 0..124 rows (32 groups x 4)
    const int tc   = (tid & 15) << 3;   // 0..120 cols
    const int row0 = blockIdx.x * 128;

    float acc[4][8];
#pragma unroll
    for (int i = 0; i < 4; i++)
#pragma unroll
        for (int j = 0; j < 8; j++) acc[i][j] = 0.0f;

    for (int kk = 0; kk < 128; kk += 32) {
        // x tile: 128 x 32 = 1024 float4 -> 2 per thread
#pragma unroll
        for (int i = 0; i < 2; i++) {
            int f4 = tid + i * 512;
            int r  = f4 >> 3;
            int kc = (f4 & 7) << 2;
            int gr = row0 + r;
            float4 v = make_float4(0.f, 0.f, 0.f, 0.f);
            if (gr < N_NODES)
                v = *(const float4*)&x[(size_t)gr * D + kk + kc];
            xs[r][kc + 0] = v.x; xs[r][kc + 1] = v.y;
            xs[r][kc + 2] = v.z; xs[r][kc + 3] = v.w;
        }
        // W tile: 32 x 128 = 1024 float4 -> 2 per thread
#pragma unroll
        for (int i = 0; i < 2; i++) {
            int f4 = tid + i * 512;
            int r  = f4 >> 5;
            int cc = (f4 & 31) << 2;
            *(float4*)&ws[r][cc] = *(const float4*)&W[(size_t)(kk + r) * D + cc];
        }
        __syncthreads();

#pragma unroll
        for (int k = 0; k < 32; k++) {
            float a[4], b[8];
#pragma unroll
            for (int i = 0; i < 4; i++) a[i] = xs[tr + i][k];
#pragma unroll
            for (int j = 0; j < 8; j++) b[j] = ws[k][tc + j];
#pragma unroll
            for (int i = 0; i < 4; i++)
#pragma unroll
                for (int j = 0; j < 8; j++) acc[i][j] = fmaf(a[i], b[j], acc[i][j]);
        }
        __syncthreads();
    }

#pragma unroll
    for (int i = 0; i < 4; i++) {
        int gr = row0 + tr + i;
        if (gr < N_NODES) {
            float* dst = &g_y[(size_t)gr * D + tc];
            *(float4*)&dst[0] = make_float4(acc[i][0], acc[i][1], acc[i][2], acc[i][3]);
            *(float4*)&dst[4] = make_float4(acc[i][4], acc[i][5], acc[i][6], acc[i][7]);
        }
    }
}

// ---------------------------------------------------------------------------
// Gather: one warp per node.  out[n] = bias + dis[n] * sum_{c in adj(n)} dis[c]*y[c]
__global__ __launch_bounds__(256) void gather_kernel(const float* __restrict__ bias,
                                                     float* __restrict__ out) {
    int node = blockIdx.x * 8 + (threadIdx.x >> 5);
    int lane = threadIdx.x & 31;
    if (node >= N_NODES) return;

    int start = g_ptr[node];
    int end   = g_ptr[node + 1];

    float4 acc = make_float4(0.f, 0.f, 0.f, 0.f);

    for (int base = start; base < end; base += 32) {
        int idx = base + lane;
        int cl  = (idx < end) ? g_ecol[idx] : 0;
        float wl = (idx < end) ? g_dis[cl] : 0.f;
        int m = min(32, end - base);
#pragma unroll 4
        for (int j = 0; j < m; j++) {
            int   c = __shfl_sync(0xffffffffu, cl, j);
            float w = __shfl_sync(0xffffffffu, wl, j);
            const float4 v = *(const float4*)&g_y[(size_t)c * D + lane * 4];
            acc.x = fmaf(w, v.x, acc.x);
            acc.y = fmaf(w, v.y, acc.y);
            acc.z = fmaf(w, v.z, acc.z);
            acc.w = fmaf(w, v.w, acc.w);
        }
    }

    float dr = (end > start) ? g_dis[node] : 0.f;   // deg=0 -> bias exactly
    const float4 b = ((const float4*)bias)[lane];
    float4 o;
    o.x = fmaf(dr, acc.x, b.x);
    o.y = fmaf(dr, acc.y, b.y);
    o.z = fmaf(dr, acc.z, b.z);
    o.w = fmaf(dr, acc.w, b.w);
    *(float4*)&out[(size_t)node * D + lane * 4] = o;
}

// ---------------------------------------------------------------------------
extern "C" void kernel_launch(void* const* d_in, const int* in_sizes, int n_in,
                              void* d_out, int out_size) {
    const float* x       = (const float*)d_in[0];
    const float* weight  = (const float*)d_in[1];
    const float* bias    = (const float*)d_in[2];
    const int*   edgerow = (const int*)d_in[3];
    const int*   edgecol = (const int*)d_in[4];
    float*       out     = (float*)d_out;

    zero_cnt_kernel<<<(N_NODES + 255) / 256, 256>>>();
    count_kernel<<<(N_EDGES + 255) / 256, 256>>>(edgerow);
    rsqrt_kernel<<<(N_NODES + 255) / 256, 256>>>();
    scan_kernel<<<1, 1024>>>();
    fill_kernel<<<(N_EDGES + 255) / 256, 256>>>(edgerow, edgecol);

    gemm_kernel<<<(N_NODES + 127) / 128, 512>>>(x, weight);

    gather_kernel<<<(N_NODES + 7) / 8, 256>>>(bias, out);
}

// round 3
// speedup vs baseline: 1.3936x; 1.3184x over previous
#include <cuda_runtime.h>
#include <cstdint>

#define N_NODES 50000
#define N_EDGES 1600000
#define D 128

#define SCAN_CHUNK 4096                       // per block: 1024 thr x 4
#define SCAN_BLOCKS ((N_NODES + SCAN_CHUNK - 1) / SCAN_CHUNK)   // 13

// Scratch (__device__ globals per allocation rules)
__device__ float g_y[(size_t)N_NODES * D];    // y = x @ W  (25.6 MB)
__device__ int   g_cnt[N_NODES];
__device__ float g_dis[N_NODES];
__device__ int   g_ptr[N_NODES + 1];
__device__ int   g_cur[N_NODES];
__device__ int   g_ecol[N_EDGES];
__device__ int   g_bsum[SCAN_BLOCKS];
__device__ int   g_boff[SCAN_BLOCKS];

// ---------------------------------------------------------------------------
__global__ void zero_cnt_kernel() {
    int i = blockIdx.x * blockDim.x + threadIdx.x;
    if (i < N_NODES) g_cnt[i] = 0;
}

__global__ void count_kernel(const int* __restrict__ row) {
    int i = blockIdx.x * blockDim.x + threadIdx.x;
    if (i < N_EDGES) atomicAdd(&g_cnt[row[i]], 1);
}

__global__ void rsqrt_kernel() {
    int i = blockIdx.x * blockDim.x + threadIdx.x;
    if (i < N_NODES) g_dis[i] = rsqrtf((float)g_cnt[i]);   // deg=0 -> inf (matches ref)
}

// ---------------------------------------------------------------------------
// Scan phase 1: per-block local exclusive scan (4 elems/thread) + block sums.
__global__ __launch_bounds__(1024) void scan1_kernel() {
    __shared__ int wsum[32];
    const int tid  = threadIdx.x;
    const int lane = tid & 31;
    const int wid  = tid >> 5;
    const int base = blockIdx.x * SCAN_CHUNK + tid * 4;

    int v0 = 0, v1 = 0, v2 = 0, v3 = 0;
    if (base + 3 < N_NODES) {
        int4 v = *(const int4*)&g_cnt[base];
        v0 = v.x; v1 = v.y; v2 = v.z; v3 = v.w;
    } else {
        if (base + 0 < N_NODES) v0 = g_cnt[base + 0];
        if (base + 1 < N_NODES) v1 = g_cnt[base + 1];
        if (base + 2 < N_NODES) v2 = g_cnt[base + 2];
        if (base + 3 < N_NODES) v3 = g_cnt[base + 3];
    }
    const int tsum = v0 + v1 + v2 + v3;

    // inclusive warp scan of tsum
    int s = tsum;
#pragma unroll
    for (int off = 1; off < 32; off <<= 1) {
        int t = __shfl_up_sync(0xffffffffu, s, off);
        if (lane >= off) s += t;
    }
    if (lane == 31) wsum[wid] = s;
    __syncthreads();

    // warp 0 scans the 32 warp sums (exclusive)
    if (wid == 0) {
        int w = wsum[lane];
        int ws = w;
#pragma unroll
        for (int off = 1; off < 32; off <<= 1) {
            int t = __shfl_up_sync(0xffffffffu, ws, off);
            if (lane >= off) ws += t;
        }
        wsum[lane] = ws - w;                 // exclusive warp base
        if (lane == 31) g_bsum[blockIdx.x] = ws;   // block total
    }
    __syncthreads();

    int e = wsum[wid] + (s - tsum);          // exclusive start of this thread
    if (base + 0 < N_NODES) g_ptr[base + 0] = e;
    if (base + 1 < N_NODES) g_ptr[base + 1] = e + v0;
    if (base + 2 < N_NODES) g_ptr[base + 2] = e + v0 + v1;
    if (base + 3 < N_NODES) g_ptr[base + 3] = e + v0 + v1 + v2;
}

// Scan phase 2: one warp scans SCAN_BLOCKS block sums (exclusive).
__global__ void scan2_kernel() {
    int lane = threadIdx.x;
    int v = (lane < SCAN_BLOCKS) ? g_bsum[lane] : 0;
    int s = v;
#pragma unroll
    for (int off = 1; off < 32; off <<= 1) {
        int t = __shfl_up_sync(0xffffffffu, s, off);
        if (lane >= off) s += t;
    }
    if (lane < SCAN_BLOCKS) g_boff[lane] = s - v;
    if (lane == 0) g_ptr[N_NODES] = N_EDGES;
}

// Scan phase 3: add block offsets, mirror into g_cur.
__global__ __launch_bounds__(1024) void scan3_kernel() {
    const int off  = g_boff[blockIdx.x];
    const int base = blockIdx.x * SCAN_CHUNK + threadIdx.x * 4;
#pragma unroll
    for (int j = 0; j < 4; j++) {
        int i = base + j;
        if (i < N_NODES) {
            int p = g_ptr[i] + off;
            g_ptr[i] = p;
            g_cur[i] = p;
        }
    }
}

__global__ void fill_kernel(const int* __restrict__ row, const int* __restrict__ col) {
    int i = blockIdx.x * blockDim.x + threadIdx.x;
    if (i < N_EDGES) {
        int r = row[i];
        int p = atomicAdd(&g_cur[r], 1);
        g_ecol[p] = col[i];
    }
}

// ---------------------------------------------------------------------------
// y = x @ W  (50000x128 @ 128x128 fp32).  BM=128, 512 threads, 4x8 micro-tile.
__global__ __launch_bounds__(512) void gemm_kernel(const float* __restrict__ x,
                                                   const float* __restrict__ W) {
    __shared__ float xs[128][33];
    __shared__ float ws[32][128];

    const int tid  = threadIdx.x;
    const int tr   = (tid >> 4) << 2;
    const int tc   = (tid & 15) << 3;
    const int row0 = blockIdx.x * 128;

    float acc[4][8];
#pragma unroll
    for (int i = 0; i < 4; i++)
#pragma unroll
        for (int j = 0; j < 8; j++) acc[i][j] = 0.0f;

    for (int kk = 0; kk < 128; kk += 32) {
#pragma unroll
        for (int i = 0; i < 2; i++) {
            int f4 = tid + i * 512;
            int r  = f4 >> 3;
            int kc = (f4 & 7) << 2;
            int gr = row0 + r;
            float4 v = make_float4(0.f, 0.f, 0.f, 0.f);
            if (gr < N_NODES)
                v = *(const float4*)&x[(size_t)gr * D + kk + kc];
            xs[r][kc + 0] = v.x; xs[r][kc + 1] = v.y;
            xs[r][kc + 2] = v.z; xs[r][kc + 3] = v.w;
        }
#pragma unroll
        for (int i = 0; i < 2; i++) {
            int f4 = tid + i * 512;
            int r  = f4 >> 5;
            int cc = (f4 & 31) << 2;
            *(float4*)&ws[r][cc] = *(const float4*)&W[(size_t)(kk + r) * D + cc];
        }
        __syncthreads();

#pragma unroll
        for (int k = 0; k < 32; k++) {
            float a[4], b[8];
#pragma unroll
            for (int i = 0; i < 4; i++) a[i] = xs[tr + i][k];
#pragma unroll
            for (int j = 0; j < 8; j++) b[j] = ws[k][tc + j];
#pragma unroll
            for (int i = 0; i < 4; i++)
#pragma unroll
                for (int j = 0; j < 8; j++) acc[i][j] = fmaf(a[i], b[j], acc[i][j]);
        }
        __syncthreads();
    }

#pragma unroll
    for (int i = 0; i < 4; i++) {
        int gr = row0 + tr + i;
        if (gr < N_NODES) {
            float* dst = &g_y[(size_t)gr * D + tc];
            *(float4*)&dst[0] = make_float4(acc[i][0], acc[i][1], acc[i][2], acc[i][3]);
            *(float4*)&dst[4] = make_float4(acc[i][4], acc[i][5], acc[i][6], acc[i][7]);
        }
    }
}

// ---------------------------------------------------------------------------
// Gather: one warp per node.  out[n] = bias + dis[n] * sum_{c in adj(n)} dis[c]*y[c]
__global__ __launch_bounds__(256) void gather_kernel(const float* __restrict__ bias,
                                                     float* __restrict__ out) {
    int node = blockIdx.x * 8 + (threadIdx.x >> 5);
    int lane = threadIdx.x & 31;
    if (node >= N_NODES) return;

    int start = g_ptr[node];
    int end   = g_ptr[node + 1];

    float4 acc = make_float4(0.f, 0.f, 0.f, 0.f);

    for (int base = start; base < end; base += 32) {
        int idx = base + lane;
        int cl  = (idx < end) ? g_ecol[idx] : 0;
        float wl = (idx < end) ? g_dis[cl] : 0.f;
        int m = min(32, end - base);
#pragma unroll 4
        for (int j = 0; j < m; j++) {
            int   c = __shfl_sync(0xffffffffu, cl, j);
            float w = __shfl_sync(0xffffffffu, wl, j);
            const float4 v = *(const float4*)&g_y[(size_t)c * D + lane * 4];
            acc.x = fmaf(w, v.x, acc.x);
            acc.y = fmaf(w, v.y, acc.y);
            acc.z = fmaf(w, v.z, acc.z);
            acc.w = fmaf(w, v.w, acc.w);
        }
    }

    float dr = (end > start) ? g_dis[node] : 0.f;   // deg=0 -> bias exactly
    const float4 b = ((const float4*)bias)[lane];
    float4 o;
    o.x = fmaf(dr, acc.x, b.x);
    o.y = fmaf(dr, acc.y, b.y);
    o.z = fmaf(dr, acc.z, b.z);
    o.w = fmaf(dr, acc.w, b.w);
    *(float4*)&out[(size_t)node * D + lane * 4] = o;
}

// ---------------------------------------------------------------------------
extern "C" void kernel_launch(void* const* d_in, const int* in_sizes, int n_in,
                              void* d_out, int out_size) {
    const float* x       = (const float*)d_in[0];
    const float* weight  = (const float*)d_in[1];
    const float* bias    = (const float*)d_in[2];
    const int*   edgerow = (const int*)d_in[3];
    const int*   edgecol = (const int*)d_in[4];
    float*       out     = (float*)d_out;

    zero_cnt_kernel<<<(N_NODES + 255) / 256, 256>>>();
    count_kernel<<<(N_EDGES + 255) / 256, 256>>>(edgerow);
    rsqrt_kernel<<<(N_NODES + 255) / 256, 256>>>();

    scan1_kernel<<<SCAN_BLOCKS, 1024>>>();
    scan2_kernel<<<1, 32>>>();
    scan3_kernel<<<SCAN_BLOCKS, 1024>>>();

    fill_kernel<<<(N_EDGES + 255) / 256, 256>>>(edgerow, edgecol);

    gemm_kernel<<<(N_NODES + 127) / 128, 512>>>(x, weight);

    gather_kernel<<<(N_NODES + 7) / 8, 256>>>(bias, out);
}

// round 6
// speedup vs baseline: 1.7153x; 1.2309x over previous
#include <cuda_runtime.h>
#include <cuda_fp16.h>
#include <cstdint>

#define N_NODES 50000
#define N_EDGES 1600000
#define D 128

#define SCAN_CHUNK 4096                       // per block: 1024 thr x 4
#define SCAN_BLOCKS ((N_NODES + SCAN_CHUNK - 1) / SCAN_CHUNK)   // 13

// Scratch (__device__ globals per allocation rules)
__device__ __half g_yh[(size_t)N_NODES * D];  // y = x @ W in fp16 (12.8 MB)
__device__ int   g_cnt[N_NODES];
__device__ float g_dis[N_NODES];
__device__ int   g_ptr[N_NODES + 1];
__device__ int   g_cur[N_NODES];
__device__ int   g_ecol[N_EDGES];
__device__ int   g_bsum[SCAN_BLOCKS];
__device__ int   g_boff[SCAN_BLOCKS];

__device__ __forceinline__ uint32_t pack_h2(float a, float b) {
    __half2 h = __floats2half2_rn(a, b);
    return *reinterpret_cast<uint32_t*>(&h);
}

// ---------------------------------------------------------------------------
__global__ void zero_cnt_kernel() {
    int i = blockIdx.x * blockDim.x + threadIdx.x;
    if (i < N_NODES) g_cnt[i] = 0;
}

__global__ void count_kernel(const int* __restrict__ row) {
    int i = blockIdx.x * blockDim.x + threadIdx.x;
    if (i < N_EDGES) atomicAdd(&g_cnt[row[i]], 1);
}

// ---------------------------------------------------------------------------
// Scan phase 1: local exclusive scan (4/thread) + block sums + fused rsqrt.
__global__ __launch_bounds__(1024) void scan1_kernel() {
    __shared__ int wsum[32];
    const int tid  = threadIdx.x;
    const int lane = tid & 31;
    const int wid  = tid >> 5;
    const int base = blockIdx.x * SCAN_CHUNK + tid * 4;

    int v0 = 0, v1 = 0, v2 = 0, v3 = 0;
    if (base + 3 < N_NODES) {
        int4 v = *(const int4*)&g_cnt[base];
        v0 = v.x; v1 = v.y; v2 = v.z; v3 = v.w;
    } else {
        if (base + 0 < N_NODES) v0 = g_cnt[base + 0];
        if (base + 1 < N_NODES) v1 = g_cnt[base + 1];
        if (base + 2 < N_NODES) v2 = g_cnt[base + 2];
        if (base + 3 < N_NODES) v3 = g_cnt[base + 3];
    }

    // fused: dis = deg^-1/2 (deg=0 -> inf, matches reference semantics)
    if (base + 0 < N_NODES) g_dis[base + 0] = rsqrtf((float)v0);
    if (base + 1 < N_NODES) g_dis[base + 1] = rsqrtf((float)v1);
    if (base + 2 < N_NODES) g_dis[base + 2] = rsqrtf((float)v2);
    if (base + 3 < N_NODES) g_dis[base + 3] = rsqrtf((float)v3);

    const int tsum = v0 + v1 + v2 + v3;

    int s = tsum;
#pragma unroll
    for (int off = 1; off < 32; off <<= 1) {
        int t = __shfl_up_sync(0xffffffffu, s, off);
        if (lane >= off) s += t;
    }
    if (lane == 31) wsum[wid] = s;
    __syncthreads();

    if (wid == 0) {
        int w = wsum[lane];
        int ws = w;
#pragma unroll
        for (int off = 1; off < 32; off <<= 1) {
            int t = __shfl_up_sync(0xffffffffu, ws, off);
            if (lane >= off) ws += t;
        }
        wsum[lane] = ws - w;
        if (lane == 31) g_bsum[blockIdx.x] = ws;
    }
    __syncthreads();

    int e = wsum[wid] + (s - tsum);
    if (base + 0 < N_NODES) g_ptr[base + 0] = e;
    if (base + 1 < N_NODES) g_ptr[base + 1] = e + v0;
    if (base + 2 < N_NODES) g_ptr[base + 2] = e + v0 + v1;
    if (base + 3 < N_NODES) g_ptr[base + 3] = e + v0 + v1 + v2;
}

__global__ void scan2_kernel() {
    int lane = threadIdx.x;
    int v = (lane < SCAN_BLOCKS) ? g_bsum[lane] : 0;
    int s = v;
#pragma unroll
    for (int off = 1; off < 32; off <<= 1) {
        int t = __shfl_up_sync(0xffffffffu, s, off);
        if (lane >= off) s += t;
    }
    if (lane < SCAN_BLOCKS) g_boff[lane] = s - v;
    if (lane == 0) g_ptr[N_NODES] = N_EDGES;
}

__global__ __launch_bounds__(1024) void scan3_kernel() {
    const int off  = g_boff[blockIdx.x];
    const int base = blockIdx.x * SCAN_CHUNK + threadIdx.x * 4;
#pragma unroll
    for (int j = 0; j < 4; j++) {
        int i = base + j;
        if (i < N_NODES) {
            int p = g_ptr[i] + off;
            g_ptr[i] = p;
            g_cur[i] = p;
        }
    }
}

__global__ void fill_kernel(const int* __restrict__ row, const int* __restrict__ col) {
    int i = blockIdx.x * blockDim.x + threadIdx.x;
    if (i < N_EDGES) {
        int r = row[i];
        int p = atomicAdd(&g_cur[r], 1);
        g_ecol[p] = col[i];
    }
}

// ---------------------------------------------------------------------------
// y = x @ W  (fp32 compute, fp16 store).  BM=128, 512 threads, 4x8 micro-tile.
__global__ __launch_bounds__(512) void gemm_kernel(const float* __restrict__ x,
                                                   const float* __restrict__ W) {
    __shared__ float xs[128][33];
    __shared__ float ws[32][128];

    const int tid  = threadIdx.x;
    const int tr   = (tid >> 4) << 2;
    const int tc   = (tid & 15) << 3;
    const int row0 = blockIdx.x * 128;

    float acc[4][8];
#pragma unroll
    for (int i = 0; i < 4; i++)
#pragma unroll
        for (int j = 0; j < 8; j++) acc[i][j] = 0.0f;

    for (int kk = 0; kk < 128; kk += 32) {
#pragma unroll
        for (int i = 0; i < 2; i++) {
            int f4 = tid + i * 512;
            int r  = f4 >> 3;
            int kc = (f4 & 7) << 2;
            int gr = row0 + r;
            float4 v = make_float4(0.f, 0.f, 0.f, 0.f);
            if (gr < N_NODES)
                v = *(const float4*)&x[(size_t)gr * D + kk + kc];
            xs[r][kc + 0] = v.x; xs[r][kc + 1] = v.y;
            xs[r][kc + 2] = v.z; xs[r][kc + 3] = v.w;
        }
#pragma unroll
        for (int i = 0; i < 2; i++) {
            int f4 = tid + i * 512;
            int r  = f4 >> 5;
            int cc = (f4 & 31) << 2;
            *(float4*)&ws[r][cc] = *(const float4*)&W[(size_t)(kk + r) * D + cc];
        }
        __syncthreads();

#pragma unroll
        for (int k = 0; k < 32; k++) {
            float a[4], b[8];
#pragma unroll
            for (int i = 0; i < 4; i++) a[i] = xs[tr + i][k];
#pragma unroll
            for (int j = 0; j < 8; j++) b[j] = ws[k][tc + j];
#pragma unroll
            for (int i = 0; i < 4; i++)
#pragma unroll
                for (int j = 0; j < 8; j++) acc[i][j] = fmaf(a[i], b[j], acc[i][j]);
        }
        __syncthreads();
    }

#pragma unroll
    for (int i = 0; i < 4; i++) {
        int gr = row0 + tr + i;
        if (gr < N_NODES) {
            uint4 packed;
            packed.x = pack_h2(acc[i][0], acc[i][1]);
            packed.y = pack_h2(acc[i][2], acc[i][3]);
            packed.z = pack_h2(acc[i][4], acc[i][5]);
            packed.w = pack_h2(acc[i][6], acc[i][7]);
            *reinterpret_cast<uint4*>(&g_yh[(size_t)gr * D + tc]) = packed;
        }
    }
}

// ---------------------------------------------------------------------------
// Gather: warp/node.  out[n] = bias + dis[n] * sum_{c in adj(n)} dis[c]*y[c]
__global__ __launch_bounds__(256) void gather_kernel(const float* __restrict__ bias,
                                                     float* __restrict__ out) {
    int node = blockIdx.x * 8 + (threadIdx.x >> 5);
    int lane = threadIdx.x & 31;
    if (node >= N_NODES) return;

    int start = g_ptr[node];
    int end   = g_ptr[node + 1];

    float4 acc = make_float4(0.f, 0.f, 0.f, 0.f);

    for (int base = start; base < end; base += 32) {
        int idx = base + lane;
        int cl  = (idx < end) ? g_ecol[idx] : 0;
        float wl = (idx < end) ? g_dis[cl] : 0.f;
        int m = min(32, end - base);
#pragma unroll 4
        for (int j = 0; j < m; j++) {
            int   c = __shfl_sync(0xffffffffu, cl, j);
            float w = __shfl_sync(0xffffffffu, wl, j);
            const uint2 v = *(const uint2*)&g_yh[(size_t)c * D + lane * 4];
            const float2 f0 = __half22float2(*(const __half2*)&v.x);
            const float2 f1 = __half22float2(*(const __half2*)&v.y);
            acc.x = fmaf(w, f0.x, acc.x);
            acc.y = fmaf(w, f0.y, acc.y);
            acc.z = fmaf(w, f1.x, acc.z);
            acc.w = fmaf(w, f1.y, acc.w);
        }
    }

    float dr = (end > start) ? g_dis[node] : 0.f;   // deg=0 -> bias exactly
    const float4 b = ((const float4*)bias)[lane];
    float4 o;
    o.x = fmaf(dr, acc.x, b.x);
    o.y = fmaf(dr, acc.y, b.y);
    o.z = fmaf(dr, acc.z, b.z);
    o.w = fmaf(dr, acc.w, b.w);
    *(float4*)&out[(size_t)node * D + lane * 4] = o;
}

// ---------------------------------------------------------------------------
extern "C" void kernel_launch(void* const* d_in, const int* in_sizes, int n_in,
                              void* d_out, int out_size) {
    const float* x       = (const float*)d_in[0];
    const float* weight  = (const float*)d_in[1];
    const float* bias    = (const float*)d_in[2];
    const int*   edgerow = (const int*)d_in[3];
    const int*   edgecol = (const int*)d_in[4];
    float*       out     = (float*)d_out;

    // Side stream + events for GEMM || CSR-build fork. Created once, on the
    // first (uncaptured correctness) call; reused inside graph capture.
    // Host-side resources only — no device memory is allocated.
    static cudaStream_t s_side = nullptr;
    static cudaEvent_t  e_fork = nullptr, e_join = nullptr;
    if (s_side == nullptr) {
        cudaStreamCreateWithFlags(&s_side, cudaStreamNonBlocking);
        cudaEventCreateWithFlags(&e_fork, cudaEventDisableTiming);
        cudaEventCreateWithFlags(&e_join, cudaEventDisableTiming);
    }

    // Fork: GEMM (depends only on x, W) runs concurrently with CSR build.
    cudaEventRecord(e_fork, 0);
    cudaStreamWaitEvent(s_side, e_fork, 0);
    gemm_kernel<<<(N_NODES + 127) / 128, 512, 0, s_side>>>(x, weight);
    cudaEventRecord(e_join, s_side);

    // CSR build chain on the main (captured) stream.
    zero_cnt_kernel<<<(N_NODES + 255) / 256, 256>>>();
    count_kernel<<<(N_EDGES + 255) / 256, 256>>>(edgerow);
    scan1_kernel<<<SCAN_BLOCKS, 1024>>>();
    scan2_kernel<<<1, 32>>>();
    scan3_kernel<<<SCAN_BLOCKS, 1024>>>();
    fill_kernel<<<(N_EDGES + 255) / 256, 256>>>(edgerow, edgecol);

    // Join: gather needs both the CSR and y.
    cudaStreamWaitEvent(0, e_join, 0);
    gather_kernel<<<(N_NODES + 7) / 8, 256>>>(bias, out);
}

// round 7
// speedup vs baseline: 2.0322x; 1.1847x over previous
#include <cuda_runtime.h>
#include <cuda_fp16.h>
#include <cstdint>

#define N_NODES 50000
#define N_EDGES 1600000
#define D 128

#define SCAN_CHUNK 4096
#define SCAN_BLOCKS ((N_NODES + SCAN_CHUNK - 1) / SCAN_CHUNK)   // 13

#define GEMM_STRIDE 132   // 132 % 32 == 4 -> conflict-free fragment LDS
#define GEMM_SMEM (2 * 128 * GEMM_STRIDE * 4)   // 135168 B

// Scratch (__device__ globals per allocation rules)
__device__ __half g_yh[(size_t)N_NODES * D];  // y = x @ W in fp16 (12.8 MB)
__device__ int   g_cnt[N_NODES];
__device__ float g_dis[N_NODES];
__device__ int   g_ptr[N_NODES + 1];
__device__ int   g_cur[N_NODES];
__device__ int   g_ecol[N_EDGES];
__device__ int   g_bsum[SCAN_BLOCKS];
__device__ int   g_boff[SCAN_BLOCKS];

__device__ __forceinline__ uint32_t pack_h2(float a, float b) {
    __half2 h = __floats2half2_rn(a, b);
    return *reinterpret_cast<uint32_t*>(&h);
}

__device__ __forceinline__ uint32_t f2tf32(float f) {
    uint32_t r;
    asm("cvt.rna.tf32.f32 %0, %1;" : "=r"(r) : "f"(f));
    return r;
}

// ---------------------------------------------------------------------------
__global__ void zero_cnt_kernel() {
    int i = blockIdx.x * blockDim.x + threadIdx.x;
    if (i < N_NODES) g_cnt[i] = 0;
}

__global__ void count_kernel(const int* __restrict__ row) {
    int i = blockIdx.x * blockDim.x + threadIdx.x;
    if (i < N_EDGES) atomicAdd(&g_cnt[row[i]], 1);
}

// ---------------------------------------------------------------------------
// Scan phase 1: local exclusive scan (4/thread) + block sums + fused rsqrt.
__global__ __launch_bounds__(1024) void scan1_kernel() {
    __shared__ int wsum[32];
    const int tid  = threadIdx.x;
    const int lane = tid & 31;
    const int wid  = tid >> 5;
    const int base = blockIdx.x * SCAN_CHUNK + tid * 4;

    int v0 = 0, v1 = 0, v2 = 0, v3 = 0;
    if (base + 3 < N_NODES) {
        int4 v = *(const int4*)&g_cnt[base];
        v0 = v.x; v1 = v.y; v2 = v.z; v3 = v.w;
    } else {
        if (base + 0 < N_NODES) v0 = g_cnt[base + 0];
        if (base + 1 < N_NODES) v1 = g_cnt[base + 1];
        if (base + 2 < N_NODES) v2 = g_cnt[base + 2];
        if (base + 3 < N_NODES) v3 = g_cnt[base + 3];
    }

    if (base + 0 < N_NODES) g_dis[base + 0] = rsqrtf((float)v0);
    if (base + 1 < N_NODES) g_dis[base + 1] = rsqrtf((float)v1);
    if (base + 2 < N_NODES) g_dis[base + 2] = rsqrtf((float)v2);
    if (base + 3 < N_NODES) g_dis[base + 3] = rsqrtf((float)v3);

    const int tsum = v0 + v1 + v2 + v3;

    int s = tsum;
#pragma unroll
    for (int off = 1; off < 32; off <<= 1) {
        int t = __shfl_up_sync(0xffffffffu, s, off);
        if (lane >= off) s += t;
    }
    if (lane == 31) wsum[wid] = s;
    __syncthreads();

    if (wid == 0) {
        int w = wsum[lane];
        int ws = w;
#pragma unroll
        for (int off = 1; off < 32; off <<= 1) {
            int t = __shfl_up_sync(0xffffffffu, ws, off);
            if (lane >= off) ws += t;
        }
        wsum[lane] = ws - w;
        if (lane == 31) g_bsum[blockIdx.x] = ws;
    }
    __syncthreads();

    int e = wsum[wid] + (s - tsum);
    if (base + 0 < N_NODES) g_ptr[base + 0] = e;
    if (base + 1 < N_NODES) g_ptr[base + 1] = e + v0;
    if (base + 2 < N_NODES) g_ptr[base + 2] = e + v0 + v1;
    if (base + 3 < N_NODES) g_ptr[base + 3] = e + v0 + v1 + v2;
}

__global__ void scan2_kernel() {
    int lane = threadIdx.x;
    int v = (lane < SCAN_BLOCKS) ? g_bsum[lane] : 0;
    int s = v;
#pragma unroll
    for (int off = 1; off < 32; off <<= 1) {
        int t = __shfl_up_sync(0xffffffffu, s, off);
        if (lane >= off) s += t;
    }
    if (lane < SCAN_BLOCKS) g_boff[lane] = s - v;
    if (lane == 0) g_ptr[N_NODES] = N_EDGES;
}

__global__ __launch_bounds__(1024) void scan3_kernel() {
    const int off  = g_boff[blockIdx.x];
    const int base = blockIdx.x * SCAN_CHUNK + threadIdx.x * 4;
#pragma unroll
    for (int j = 0; j < 4; j++) {
        int i = base + j;
        if (i < N_NODES) {
            int p = g_ptr[i] + off;
            g_ptr[i] = p;
            g_cur[i] = p;
        }
    }
}

__global__ void fill_kernel(const int* __restrict__ row, const int* __restrict__ col) {
    int i = blockIdx.x * blockDim.x + threadIdx.x;
    if (i < N_EDGES) {
        int r = row[i];
        int p = atomicAdd(&g_cur[r], 1);
        g_ecol[p] = col[i];
    }
}

// ---------------------------------------------------------------------------
// y = x @ W via tf32 mma.sync.m16n8k8, fp32 accumulate, fp16 store.
// 512 threads = 16 warps = 8(M) x 2(N). Block tile 128x128, full K=128 resident.
// smem: xs[128][132] (x as tf32 bits), wst[128][132] (W transposed, tf32 bits).
__global__ __launch_bounds__(512) void gemm_kernel(const float* __restrict__ x,
                                                   const float* __restrict__ W) {
    extern __shared__ uint32_t sm[];
    uint32_t* xs  = sm;                       // [row][k]  stride GEMM_STRIDE
    uint32_t* wst = sm + 128 * GEMM_STRIDE;   // [n][k]    stride GEMM_STRIDE

    const int tid  = threadIdx.x;
    const int lane = tid & 31;
    const int wid  = tid >> 5;
    const int gid  = lane >> 2;    // 0..7
    const int tig  = lane & 3;     // 0..3
    const int wm   = wid & 7;      // warp M index (16 rows each)
    const int wn   = wid >> 3;     // warp N index (64 cols each)
    const int row0 = blockIdx.x * 128;

    // ---- load x tile (128 rows x 128 k) -> xs, cvt to tf32 ----
#pragma unroll
    for (int i = 0; i < 8; i++) {
        int f  = tid + i * 512;         // float4 index, 32 per row
        int r  = f >> 5;
        int c4 = (f & 31) << 2;
        int gr = row0 + r;
        float4 v = make_float4(0.f, 0.f, 0.f, 0.f);
        if (gr < N_NODES) v = *(const float4*)&x[(size_t)gr * D + c4];
        uint32_t* dst = &xs[r * GEMM_STRIDE + c4];
        dst[0] = f2tf32(v.x); dst[1] = f2tf32(v.y);
        dst[2] = f2tf32(v.z); dst[3] = f2tf32(v.w);
    }
    // ---- load W (128k x 128n) transposed -> wst[n][k], cvt to tf32 ----
#pragma unroll
    for (int i = 0; i < 8; i++) {
        int f  = tid + i * 512;
        int k  = f >> 5;
        int n4 = (f & 31) << 2;
        float4 v = *(const float4*)&W[(size_t)k * D + n4];
        wst[(n4 + 0) * GEMM_STRIDE + k] = f2tf32(v.x);
        wst[(n4 + 1) * GEMM_STRIDE + k] = f2tf32(v.y);
        wst[(n4 + 2) * GEMM_STRIDE + k] = f2tf32(v.z);
        wst[(n4 + 3) * GEMM_STRIDE + k] = f2tf32(v.w);
    }
    __syncthreads();

    // ---- mma mainloop: 16 k-steps of k8, 8 n-tiles of n8 per warp ----
    float c[8][4];
#pragma unroll
    for (int t = 0; t < 8; t++)
#pragma unroll
        for (int j = 0; j < 4; j++) c[t][j] = 0.0f;

    const int arow = wm * 16 + gid;
#pragma unroll
    for (int k0 = 0; k0 < 16; k0++) {
        const int kb = k0 * 8;
        uint32_t a0 = xs[(arow)     * GEMM_STRIDE + kb + tig];
        uint32_t a1 = xs[(arow + 8) * GEMM_STRIDE + kb + tig];
        uint32_t a2 = xs[(arow)     * GEMM_STRIDE + kb + tig + 4];
        uint32_t a3 = xs[(arow + 8) * GEMM_STRIDE + kb + tig + 4];
#pragma unroll
        for (int t = 0; t < 8; t++) {
            const int n = wn * 64 + t * 8 + gid;
            uint32_t b0 = wst[n * GEMM_STRIDE + kb + tig];
            uint32_t b1 = wst[n * GEMM_STRIDE + kb + tig + 4];
            asm volatile(
                "mma.sync.aligned.m16n8k8.row.col.f32.tf32.tf32.f32 "
                "{%0,%1,%2,%3}, {%4,%5,%6,%7}, {%8,%9}, {%0,%1,%2,%3};"
                : "+f"(c[t][0]), "+f"(c[t][1]), "+f"(c[t][2]), "+f"(c[t][3])
                : "r"(a0), "r"(a1), "r"(a2), "r"(a3), "r"(b0), "r"(b1));
        }
    }

    // ---- epilogue: fp32 -> fp16 pairs, store to g_yh ----
    const int grow0 = row0 + wm * 16 + gid;       // row for c0,c1
    const int grow1 = grow0 + 8;                  // row for c2,c3
#pragma unroll
    for (int t = 0; t < 8; t++) {
        const int col = wn * 64 + t * 8 + tig * 2;
        if (grow0 < N_NODES)
            *reinterpret_cast<uint32_t*>(&g_yh[(size_t)grow0 * D + col]) = pack_h2(c[t][0], c[t][1]);
        if (grow1 < N_NODES)
            *reinterpret_cast<uint32_t*>(&g_yh[(size_t)grow1 * D + col]) = pack_h2(c[t][2], c[t][3]);
    }
}

// ---------------------------------------------------------------------------
// Gather: warp/node.  out[n] = bias + dis[n] * sum_{c in adj(n)} dis[c]*y[c]
__global__ __launch_bounds__(256) void gather_kernel(const float* __restrict__ bias,
                                                     float* __restrict__ out) {
    int node = blockIdx.x * 8 + (threadIdx.x >> 5);
    int lane = threadIdx.x & 31;
    if (node >= N_NODES) return;

    int start = g_ptr[node];
    int end   = g_ptr[node + 1];

    float4 acc = make_float4(0.f, 0.f, 0.f, 0.f);

    for (int base = start; base < end; base += 32) {
        int idx = base + lane;
        int cl  = (idx < end) ? g_ecol[idx] : 0;
        float wl = (idx < end) ? g_dis[cl] : 0.f;
        int m = min(32, end - base);
#pragma unroll 4
        for (int j = 0; j < m; j++) {
            int   c = __shfl_sync(0xffffffffu, cl, j);
            float w = __shfl_sync(0xffffffffu, wl, j);
            const uint2 v = *(const uint2*)&g_yh[(size_t)c * D + lane * 4];
            const float2 f0 = __half22float2(*(const __half2*)&v.x);
            const float2 f1 = __half22float2(*(const __half2*)&v.y);
            acc.x = fmaf(w, f0.x, acc.x);
            acc.y = fmaf(w, f0.y, acc.y);
            acc.z = fmaf(w, f1.x, acc.z);
            acc.w = fmaf(w, f1.y, acc.w);
        }
    }

    float dr = (end > start) ? g_dis[node] : 0.f;   // deg=0 -> bias exactly
    const float4 b = ((const float4*)bias)[lane];
    float4 o;
    o.x = fmaf(dr, acc.x, b.x);
    o.y = fmaf(dr, acc.y, b.y);
    o.z = fmaf(dr, acc.z, b.z);
    o.w = fmaf(dr, acc.w, b.w);
    *(float4*)&out[(size_t)node * D + lane * 4] = o;
}

// ---------------------------------------------------------------------------
extern "C" void kernel_launch(void* const* d_in, const int* in_sizes, int n_in,
                              void* d_out, int out_size) {
    const float* x       = (const float*)d_in[0];
    const float* weight  = (const float*)d_in[1];
    const float* bias    = (const float*)d_in[2];
    const int*   edgerow = (const int*)d_in[3];
    const int*   edgecol = (const int*)d_in[4];
    float*       out     = (float*)d_out;

    // One-time host-side setup (first call is the uncaptured correctness run).
    static cudaStream_t s_side = nullptr;
    static cudaEvent_t  e_fork = nullptr, e_join = nullptr;
    if (s_side == nullptr) {
        cudaStreamCreateWithFlags(&s_side, cudaStreamNonBlocking);
        cudaEventCreateWithFlags(&e_fork, cudaEventDisableTiming);
        cudaEventCreateWithFlags(&e_join, cudaEventDisableTiming);
        cudaFuncSetAttribute(gemm_kernel,
                             cudaFuncAttributeMaxDynamicSharedMemorySize, GEMM_SMEM);
    }

    // Fork: GEMM (x, W only) alongside CSR build.
    cudaEventRecord(e_fork, 0);
    cudaStreamWaitEvent(s_side, e_fork, 0);
    gemm_kernel<<<(N_NODES + 127) / 128, 512, GEMM_SMEM, s_side>>>(x, weight);
    cudaEventRecord(e_join, s_side);

    // CSR build chain on the main (captured) stream.
    zero_cnt_kernel<<<(N_NODES + 255) / 256, 256>>>();
    count_kernel<<<(N_EDGES + 255) / 256, 256>>>(edgerow);
    scan1_kernel<<<SCAN_BLOCKS, 1024>>>();
    scan2_kernel<<<1, 32>>>();
    scan3_kernel<<<SCAN_BLOCKS, 1024>>>();
    fill_kernel<<<(N_EDGES + 255) / 256, 256>>>(edgerow, edgecol);

    // Join: gather needs both the CSR and y.
    cudaStreamWaitEvent(0, e_join, 0);
    gather_kernel<<<(N_NODES + 7) / 8, 256>>>(bias, out);
}